// round 4
// baseline (speedup 1.0000x reference)
#include <cuda_runtime.h>
#include <cuda_bf16.h>
#include <cstdint>

// ---------------------------------------------------------------------------
// GCNEncoder: 8-layer GCN, N=100000, E=1.6M, F=15->64(x7)->64
// Fused layer kernel exploiting linearity:  act(agg(h@W)+b) == act(agg(h)@W+b)
//   - one warp per node: CSR gather+aggregate h rows (L2-bound)
//   - epilogue: per-node matvec vs smem-resident W (overlaps with gather stalls)
// Removes all standalone GEMMs and the intermediate t write/read traffic.
// edge_index is int32 on device (JAX default, x64 disabled).
// ---------------------------------------------------------------------------

#define MAXN 131072
#define MAXE 1700000

__device__ float g_h0[MAXN * 64];
__device__ float g_h1[MAXN * 64];
__device__ float g_deg[MAXN];
__device__ float g_dinv[MAXN];
__device__ float g_selfnorm[MAXN];
__device__ int   g_cnt[MAXN];
__device__ int   g_cursor[MAXN];
__device__ int   g_rowoff[MAXN + 1];
__device__ int   g_bsum[256];
__device__ int   g_esrc[MAXE];
__device__ float g_enorm[MAXE];

// ------------------------------ preprocessing ------------------------------

__global__ void k_init(int N) {
    int i = blockIdx.x * blockDim.x + threadIdx.x;
    if (i < N) {
        g_deg[i] = 1.0f;   // self-loop weight
        g_cnt[i] = 0;
        g_cursor[i] = 0;
    }
}

__global__ void k_edge_deg(const int* __restrict__ ei,
                           const float* __restrict__ ew, int E, int N) {
    int i = blockIdx.x * blockDim.x + threadIdx.x;
    if (i >= E) return;
    int d = ei[E + i];
    if ((unsigned)d >= (unsigned)N) return;
    atomicAdd(&g_deg[d], ew[i]);
    atomicAdd(&g_cnt[d], 1);
}

__global__ void k_dinv(int N) {
    int i = blockIdx.x * blockDim.x + threadIdx.x;
    if (i < N) {
        float dg = g_deg[i];
        float r = (dg > 0.0f) ? rsqrtf(dg) : 0.0f;
        g_dinv[i] = r;
        g_selfnorm[i] = r * r;
    }
}

// scan step A: per-1024-chunk sums
__global__ void k_scan_reduce(int N) {
    __shared__ int sdata[256];
    int b = blockIdx.x;
    int base = b * 1024;
    int sum = 0;
    for (int i = threadIdx.x; i < 1024; i += 256) {
        int g = base + i;
        sum += (g < N) ? g_cnt[g] : 0;
    }
    sdata[threadIdx.x] = sum;
    __syncthreads();
    for (int s = 128; s > 0; s >>= 1) {
        if (threadIdx.x < s) sdata[threadIdx.x] += sdata[threadIdx.x + s];
        __syncthreads();
    }
    if (threadIdx.x == 0) g_bsum[b] = sdata[0];
}

// scan step B: exclusive scan of chunk sums (NB <= 128)
__global__ void k_scan_bsum(int NB, int N, int E) {
    __shared__ int sh[128];
    int t = threadIdx.x;
    if (t < NB) sh[t] = g_bsum[t];
    __syncthreads();
    if (t == 0) {
        int run = 0;
        for (int i = 0; i < NB; i++) { int x = sh[i]; sh[i] = run; run += x; }
    }
    __syncthreads();
    if (t < NB) g_bsum[t] = sh[t];
    if (t == 0) g_rowoff[N] = E;
}

// scan step C: per-chunk exclusive scan + chunk base -> row offsets
__global__ void k_scan_chunks(int N) {
    int b = blockIdx.x;
    int t = threadIdx.x;
    int g0 = b * 1024 + 4 * t;
    int v0 = (g0 + 0 < N) ? g_cnt[g0 + 0] : 0;
    int v1 = (g0 + 1 < N) ? g_cnt[g0 + 1] : 0;
    int v2 = (g0 + 2 < N) ? g_cnt[g0 + 2] : 0;
    int v3 = (g0 + 3 < N) ? g_cnt[g0 + 3] : 0;
    int s = v0 + v1 + v2 + v3;
    int lane = t & 31, wid = t >> 5;
    int incl = s;
#pragma unroll
    for (int o = 1; o < 32; o <<= 1) {
        int x = __shfl_up_sync(0xffffffffu, incl, o);
        if (lane >= o) incl += x;
    }
    __shared__ int wsum[8];
    __shared__ int woff[8];
    if (lane == 31) wsum[wid] = incl;
    __syncthreads();
    if (t == 0) {
        int run = 0;
        for (int i = 0; i < 8; i++) { int x = wsum[i]; woff[i] = run; run += x; }
    }
    __syncthreads();
    int excl = g_bsum[b] + woff[wid] + (incl - s);
    if (g0 + 0 < N) g_rowoff[g0 + 0] = excl;
    if (g0 + 1 < N) g_rowoff[g0 + 1] = excl + v0;
    if (g0 + 2 < N) g_rowoff[g0 + 2] = excl + v0 + v1;
    if (g0 + 3 < N) g_rowoff[g0 + 3] = excl + v0 + v1 + v2;
}

__global__ void k_fill(const int* __restrict__ ei,
                       const float* __restrict__ ew, int E, int N) {
    int i = blockIdx.x * blockDim.x + threadIdx.x;
    if (i >= E) return;
    int s = ei[i];
    int d = ei[E + i];
    if ((unsigned)s >= (unsigned)N || (unsigned)d >= (unsigned)N) return;
    float nm = g_dinv[s] * ew[i] * g_dinv[d];
    int pos = g_rowoff[d] + atomicAdd(&g_cursor[d], 1);
    if ((unsigned)pos < (unsigned)MAXE) {
        g_esrc[pos] = s;
        g_enorm[pos] = nm;
    }
}

// ------------------------------- fused layer --------------------------------
// One warp per node (grid-stride). FIN=64: lane holds 2 features (float2).
// FIN=15: lane<15 holds 1 feature. After aggregation, stage a[] in smem and
// apply out = a @ W + b, then act. act: 1=relu, 2=sigmoid.

template <int FIN>
__global__ void __launch_bounds__(256) k_layer(
    const float* __restrict__ hin, const float* __restrict__ W,
    const float* __restrict__ bias, float* __restrict__ hout,
    int N, int act)
{
    __shared__ __align__(16) float Ws[FIN][66];   // W[k][f], padded row
    __shared__ __align__(16) float As[8][68];     // per-warp aggregated feats

    int t = threadIdx.x;
    for (int i = t; i < FIN * 64; i += 256) Ws[i >> 6][i & 63] = W[i];
    __syncthreads();

    int lane = t & 31, wid = t >> 5;
    float2 bv = ((const float2*)bias)[lane];
    int nW = gridDim.x * 8;

    for (int w = blockIdx.x * 8 + wid; w < N; w += nW) {
        float sn = g_selfnorm[w];
        int beg = g_rowoff[w];
        int end = g_rowoff[w + 1];

        if (FIN == 64) {
            const float2* h2 = (const float2*)hin;
            float2 self = h2[(size_t)w * 32 + lane];
            float ax = sn * self.x;
            float ay = sn * self.y;
            int j = beg;
            for (; j + 4 <= end; j += 4) {
                int s0 = g_esrc[j + 0], s1 = g_esrc[j + 1];
                int s2 = g_esrc[j + 2], s3 = g_esrc[j + 3];
                float m0 = g_enorm[j + 0], m1 = g_enorm[j + 1];
                float m2 = g_enorm[j + 2], m3 = g_enorm[j + 3];
                float2 v0 = h2[(size_t)s0 * 32 + lane];
                float2 v1 = h2[(size_t)s1 * 32 + lane];
                float2 v2 = h2[(size_t)s2 * 32 + lane];
                float2 v3 = h2[(size_t)s3 * 32 + lane];
                ax += m0 * v0.x; ay += m0 * v0.y;
                ax += m1 * v1.x; ay += m1 * v1.y;
                ax += m2 * v2.x; ay += m2 * v2.y;
                ax += m3 * v3.x; ay += m3 * v3.y;
            }
            for (; j < end; j++) {
                int s = g_esrc[j];
                float m = g_enorm[j];
                float2 v = h2[(size_t)s * 32 + lane];
                ax += m * v.x; ay += m * v.y;
            }
            As[wid][2 * lane + 0] = ax;
            As[wid][2 * lane + 1] = ay;
        } else {
            float self = (lane < FIN) ? hin[(size_t)w * FIN + lane] : 0.f;
            float ax = sn * self;
            int j = beg;
            for (; j + 2 <= end; j += 2) {
                int s0 = g_esrc[j + 0], s1 = g_esrc[j + 1];
                float m0 = g_enorm[j + 0], m1 = g_enorm[j + 1];
                float v0 = (lane < FIN) ? hin[(size_t)s0 * FIN + lane] : 0.f;
                float v1 = (lane < FIN) ? hin[(size_t)s1 * FIN + lane] : 0.f;
                ax += m0 * v0 + m1 * v1;
            }
            for (; j < end; j++) {
                int s = g_esrc[j];
                float m = g_enorm[j];
                float v = (lane < FIN) ? hin[(size_t)s * FIN + lane] : 0.f;
                ax += m * v;
            }
            if (lane < FIN) As[wid][lane] = ax;
        }
        __syncwarp();

        // epilogue: out[2*lane, 2*lane+1] = bias + sum_k a[k] * W[k][...]
        float ox = bv.x, oy = bv.y;
#pragma unroll
        for (int k = 0; k < FIN; k++) {
            float a = As[wid][k];                       // smem broadcast
            float2 w2 = *(const float2*)&Ws[k][2 * lane];
            ox += a * w2.x;
            oy += a * w2.y;
        }
        if (act == 1) {
            ox = fmaxf(ox, 0.f);
            oy = fmaxf(oy, 0.f);
        } else {
            ox = 1.0f / (1.0f + __expf(-ox));
            oy = 1.0f / (1.0f + __expf(-oy));
        }
        ((float2*)hout)[(size_t)w * 32 + lane] = make_float2(ox, oy);
        __syncwarp();   // protect As before next iteration's writes
    }
}

// --------------------------------- launcher --------------------------------

extern "C" void kernel_launch(void* const* d_in, const int* in_sizes, int n_in,
                              void* d_out, int out_size) {
    const float* x  = (const float*)d_in[0];
    const int*   ei = (const int*)d_in[1];     // int32 (JAX default, x64 off)
    const float* ew = (const float*)d_in[2];
    const float* W0 = (const float*)d_in[3];
    const float* b0 = (const float*)d_in[4];
    const float* Wm = (const float*)d_in[5];
    const float* bm = (const float*)d_in[6];
    const float* Wl = (const float*)d_in[7];
    const float* bl = (const float*)d_in[8];

    int N = in_sizes[0] / 15;
    int E = in_sizes[2];

    float* hA;
    float* hB;
    cudaGetSymbolAddress((void**)&hA, g_h0);
    cudaGetSymbolAddress((void**)&hB, g_h1);

    int NB = (N + 1023) / 1024;

    k_init<<<(N + 255) / 256, 256>>>(N);
    k_edge_deg<<<(E + 255) / 256, 256>>>(ei, ew, E, N);
    k_dinv<<<(N + 255) / 256, 256>>>(N);
    k_scan_reduce<<<NB, 256>>>(N);
    k_scan_bsum<<<1, 128>>>(NB, N, E);
    k_scan_chunks<<<NB, 256>>>(N);
    k_fill<<<(E + 255) / 256, 256>>>(ei, ew, E, N);

    const int GRID = 888;   // 6 blocks/SM, grid-stride over nodes

    // layer 0: h = relu(agg(x) @ W0 + b0)
    k_layer<15><<<GRID, 256>>>(x, W0, b0, hA, N, 1);

    // middle layers 1..6
    float* cur = hA;
    float* nxt = hB;
    for (int i = 0; i < 6; i++) {
        k_layer<64><<<GRID, 256>>>(cur, Wm + (size_t)i * 64 * 64,
                                   bm + (size_t)i * 64, nxt, N, 1);
        float* tmp = cur; cur = nxt; nxt = tmp;
    }

    // final layer + sigmoid -> d_out
    k_layer<64><<<GRID, 256>>>(cur, Wl, bl, (float*)d_out, N, 2);
}

// round 5
// speedup vs baseline: 1.3716x; 1.3716x over previous
#include <cuda_runtime.h>
#include <cuda_fp16.h>
#include <cstdint>

// ---------------------------------------------------------------------------
// GCNEncoder: 8-layer GCN, N=100000, E=1.6M, F=15->64(x7)->64
// Round-3 structure (separate GEMM + CSR agg) with fp16 staging of the
// transformed features t: GEMM computes in fp32, stores half2; the L2-bound
// gather in agg reads half the bytes and accumulates in fp32.
// edge_index is int32 on device (JAX default, x64 disabled).
// ---------------------------------------------------------------------------

#define MAXN 131072
#define MAXE 1700000

__device__ __half g_t[MAXN * 64];       // transformed features (fp16 staged)
__device__ float  g_h[MAXN * 64];       // layer activations (fp32)
__device__ float  g_deg[MAXN];
__device__ float  g_dinv[MAXN];
__device__ float  g_selfnorm[MAXN];
__device__ int    g_cnt[MAXN];
__device__ int    g_cursor[MAXN];
__device__ int    g_rowoff[MAXN + 1];
__device__ int    g_bsum[256];
__device__ int    g_esrc[MAXE];
__device__ float  g_enorm[MAXE];

// ------------------------------ preprocessing ------------------------------

__global__ void k_init(int N) {
    int i = blockIdx.x * blockDim.x + threadIdx.x;
    if (i < N) {
        g_deg[i] = 1.0f;   // self-loop weight
        g_cnt[i] = 0;
        g_cursor[i] = 0;
    }
}

__global__ void k_edge_deg(const int* __restrict__ ei,
                           const float* __restrict__ ew, int E, int N) {
    int i = blockIdx.x * blockDim.x + threadIdx.x;
    if (i >= E) return;
    int d = ei[E + i];
    if ((unsigned)d >= (unsigned)N) return;
    atomicAdd(&g_deg[d], ew[i]);
    atomicAdd(&g_cnt[d], 1);
}

__global__ void k_dinv(int N) {
    int i = blockIdx.x * blockDim.x + threadIdx.x;
    if (i < N) {
        float dg = g_deg[i];
        float r = (dg > 0.0f) ? rsqrtf(dg) : 0.0f;
        g_dinv[i] = r;
        g_selfnorm[i] = r * r;
    }
}

// scan step A: per-1024-chunk sums
__global__ void k_scan_reduce(int N) {
    __shared__ int sdata[256];
    int b = blockIdx.x;
    int base = b * 1024;
    int sum = 0;
    for (int i = threadIdx.x; i < 1024; i += 256) {
        int g = base + i;
        sum += (g < N) ? g_cnt[g] : 0;
    }
    sdata[threadIdx.x] = sum;
    __syncthreads();
    for (int s = 128; s > 0; s >>= 1) {
        if (threadIdx.x < s) sdata[threadIdx.x] += sdata[threadIdx.x + s];
        __syncthreads();
    }
    if (threadIdx.x == 0) g_bsum[b] = sdata[0];
}

// scan step B: exclusive scan of chunk sums (NB <= 128)
__global__ void k_scan_bsum(int NB, int N, int E) {
    __shared__ int sh[128];
    int t = threadIdx.x;
    if (t < NB) sh[t] = g_bsum[t];
    __syncthreads();
    if (t == 0) {
        int run = 0;
        for (int i = 0; i < NB; i++) { int x = sh[i]; sh[i] = run; run += x; }
    }
    __syncthreads();
    if (t < NB) g_bsum[t] = sh[t];
    if (t == 0) g_rowoff[N] = E;
}

// scan step C: per-chunk exclusive scan + chunk base -> row offsets
__global__ void k_scan_chunks(int N) {
    int b = blockIdx.x;
    int t = threadIdx.x;
    int g0 = b * 1024 + 4 * t;
    int v0 = (g0 + 0 < N) ? g_cnt[g0 + 0] : 0;
    int v1 = (g0 + 1 < N) ? g_cnt[g0 + 1] : 0;
    int v2 = (g0 + 2 < N) ? g_cnt[g0 + 2] : 0;
    int v3 = (g0 + 3 < N) ? g_cnt[g0 + 3] : 0;
    int s = v0 + v1 + v2 + v3;
    int lane = t & 31, wid = t >> 5;
    int incl = s;
#pragma unroll
    for (int o = 1; o < 32; o <<= 1) {
        int x = __shfl_up_sync(0xffffffffu, incl, o);
        if (lane >= o) incl += x;
    }
    __shared__ int wsum[8];
    __shared__ int woff[8];
    if (lane == 31) wsum[wid] = incl;
    __syncthreads();
    if (t == 0) {
        int run = 0;
        for (int i = 0; i < 8; i++) { int x = wsum[i]; woff[i] = run; run += x; }
    }
    __syncthreads();
    int excl = g_bsum[b] + woff[wid] + (incl - s);
    if (g0 + 0 < N) g_rowoff[g0 + 0] = excl;
    if (g0 + 1 < N) g_rowoff[g0 + 1] = excl + v0;
    if (g0 + 2 < N) g_rowoff[g0 + 2] = excl + v0 + v1;
    if (g0 + 3 < N) g_rowoff[g0 + 3] = excl + v0 + v1 + v2;
}

__global__ void k_fill(const int* __restrict__ ei,
                       const float* __restrict__ ew, int E, int N) {
    int i = blockIdx.x * blockDim.x + threadIdx.x;
    if (i >= E) return;
    int s = ei[i];
    int d = ei[E + i];
    if ((unsigned)s >= (unsigned)N || (unsigned)d >= (unsigned)N) return;
    float nm = g_dinv[s] * ew[i] * g_dinv[d];
    int pos = g_rowoff[d] + atomicAdd(&g_cursor[d], 1);
    if ((unsigned)pos < (unsigned)MAXE) {
        g_esrc[pos] = s;
        g_enorm[pos] = nm;
    }
}

// ------------------------------- dense GEMM --------------------------------
// C[N,64] = A[N,FIN] @ W[FIN,64], fp32 compute, fp16 store.
// 64-node tile per block, 4x4 register tile, 256 threads.

template <int FIN>
__global__ void k_transform(const float* __restrict__ A,
                            const float* __restrict__ W,
                            __half* __restrict__ C, int N) {
    __shared__ float As[FIN][68];
    __shared__ float Bs[FIN][68];
    int t = threadIdx.x;                 // 256 threads
    int n0 = blockIdx.x * 64;

    // load W -> Bs
    for (int idx = t; idx < FIN * 64; idx += 256) {
        int k = idx >> 6, f = idx & 63;
        Bs[k][f] = W[idx];
    }
    // load A tile (transposed into As[k][node])
    if (FIN == 64) {
#pragma unroll
        for (int r = 0; r < 4; r++) {
            int q = t + 256 * r;         // 0..1023 float4 slots
            int node = q >> 4;           // 0..63
            int k4 = q & 15;
            int gn = n0 + node;
            float4 v = (gn < N) ? *(const float4*)(A + (size_t)gn * 64 + 4 * k4)
                                : make_float4(0.f, 0.f, 0.f, 0.f);
            As[4 * k4 + 0][node] = v.x;
            As[4 * k4 + 1][node] = v.y;
            As[4 * k4 + 2][node] = v.z;
            As[4 * k4 + 3][node] = v.w;
        }
    } else {
        for (int idx = t; idx < 64 * FIN; idx += 256) {
            int node = idx / FIN;
            int k = idx % FIN;
            int gn = n0 + node;
            As[k][node] = (gn < N) ? A[(size_t)gn * FIN + k] : 0.f;
        }
    }
    __syncthreads();

    int tx = t & 15, ty = t >> 4;        // tx: feature quad, ty: node quad
    float acc[4][4];
#pragma unroll
    for (int i = 0; i < 4; i++)
#pragma unroll
        for (int j = 0; j < 4; j++) acc[i][j] = 0.f;

#pragma unroll 8
    for (int k = 0; k < FIN; k++) {
        float4 a = *(const float4*)&As[k][4 * ty];
        float4 b = *(const float4*)&Bs[k][4 * tx];
        float av[4] = {a.x, a.y, a.z, a.w};
        float bv[4] = {b.x, b.y, b.z, b.w};
#pragma unroll
        for (int i = 0; i < 4; i++)
#pragma unroll
            for (int j = 0; j < 4; j++) acc[i][j] += av[i] * bv[j];
    }

#pragma unroll
    for (int i = 0; i < 4; i++) {
        int gn = n0 + 4 * ty + i;
        if (gn < N) {
            __half2 p0 = __floats2half2_rn(acc[i][0], acc[i][1]);
            __half2 p1 = __floats2half2_rn(acc[i][2], acc[i][3]);
            uint2 pk;
            pk.x = *(unsigned*)&p0;
            pk.y = *(unsigned*)&p1;
            *(uint2*)(C + (size_t)gn * 64 + 4 * tx) = pk;   // 8B-aligned
        }
    }
}

// ------------------------------- aggregation -------------------------------
// One warp per node; lane holds 2 features as one half2 (4 B -> warp 128 B/edge).
// fp32 accumulation. act: 1=relu, 2=sigmoid.

__global__ void k_agg(const __half2* __restrict__ tin,
                      const float* __restrict__ bias,
                      float* __restrict__ out, int N, int act) {
    int w = (blockIdx.x * blockDim.x + threadIdx.x) >> 5;
    int lane = threadIdx.x & 31;
    if (w >= N) return;

    float2 self = __half22float2(tin[(size_t)w * 32 + lane]);
    float sn = g_selfnorm[w];
    float ax = sn * self.x;
    float ay = sn * self.y;

    int beg = g_rowoff[w];
    int end = g_rowoff[w + 1];
    int j = beg;
    for (; j + 4 <= end; j += 4) {
        int s0 = g_esrc[j + 0], s1 = g_esrc[j + 1];
        int s2 = g_esrc[j + 2], s3 = g_esrc[j + 3];
        float m0 = g_enorm[j + 0], m1 = g_enorm[j + 1];
        float m2 = g_enorm[j + 2], m3 = g_enorm[j + 3];
        float2 v0 = __half22float2(tin[(size_t)s0 * 32 + lane]);
        float2 v1 = __half22float2(tin[(size_t)s1 * 32 + lane]);
        float2 v2 = __half22float2(tin[(size_t)s2 * 32 + lane]);
        float2 v3 = __half22float2(tin[(size_t)s3 * 32 + lane]);
        ax += m0 * v0.x; ay += m0 * v0.y;
        ax += m1 * v1.x; ay += m1 * v1.y;
        ax += m2 * v2.x; ay += m2 * v2.y;
        ax += m3 * v3.x; ay += m3 * v3.y;
    }
    for (; j < end; j++) {
        int s = g_esrc[j];
        float m = g_enorm[j];
        float2 v = __half22float2(tin[(size_t)s * 32 + lane]);
        ax += m * v.x; ay += m * v.y;
    }

    float2 b = ((const float2*)bias)[lane];
    ax += b.x; ay += b.y;
    if (act == 1) {
        ax = fmaxf(ax, 0.f);
        ay = fmaxf(ay, 0.f);
    } else if (act == 2) {
        ax = 1.0f / (1.0f + __expf(-ax));
        ay = 1.0f / (1.0f + __expf(-ay));
    }
    ((float2*)out)[(size_t)w * 32 + lane] = make_float2(ax, ay);
}

// --------------------------------- launcher --------------------------------

extern "C" void kernel_launch(void* const* d_in, const int* in_sizes, int n_in,
                              void* d_out, int out_size) {
    const float* x  = (const float*)d_in[0];
    const int*   ei = (const int*)d_in[1];     // int32 (JAX default, x64 off)
    const float* ew = (const float*)d_in[2];
    const float* W0 = (const float*)d_in[3];
    const float* b0 = (const float*)d_in[4];
    const float* Wm = (const float*)d_in[5];
    const float* bm = (const float*)d_in[6];
    const float* Wl = (const float*)d_in[7];
    const float* bl = (const float*)d_in[8];

    int N = in_sizes[0] / 15;
    int E = in_sizes[2];

    __half* t;
    float*  h;
    cudaGetSymbolAddress((void**)&t, g_t);
    cudaGetSymbolAddress((void**)&h, g_h);

    int NB = (N + 1023) / 1024;

    k_init<<<(N + 255) / 256, 256>>>(N);
    k_edge_deg<<<(E + 255) / 256, 256>>>(ei, ew, E, N);
    k_dinv<<<(N + 255) / 256, 256>>>(N);
    k_scan_reduce<<<NB, 256>>>(N);
    k_scan_bsum<<<1, 128>>>(NB, N, E);
    k_scan_chunks<<<NB, 256>>>(N);
    k_fill<<<(E + 255) / 256, 256>>>(ei, ew, E, N);

    // layer 0: agg(x @ W0) + b0, relu   (transform first: 15 -> 64)
    k_transform<15><<<(N + 63) / 64, 256>>>(x, W0, t, N);
    k_agg<<<(N + 7) / 8, 256>>>((const __half2*)t, b0, h, N, 1);

    // middle layers 1..6
    for (int i = 0; i < 6; i++) {
        k_transform<64><<<(N + 63) / 64, 256>>>(h, Wm + (size_t)i * 64 * 64, t, N);
        k_agg<<<(N + 7) / 8, 256>>>((const __half2*)t, bm + (size_t)i * 64, h, N, 1);
    }

    // final layer + sigmoid -> d_out
    k_transform<64><<<(N + 63) / 64, 256>>>(h, Wl, t, N);
    k_agg<<<(N + 7) / 8, 256>>>((const __half2*)t, bl, (float*)d_out, N, 2);
}